// round 9
// baseline (speedup 1.0000x reference)
#include <cuda_runtime.h>
#include <cuda_bf16.h>

// HGNN forward, single kernel. Grid (256 graphs x 4 e-quarters), 256 threads.
//   Per block: 12 hyperedges of one graph. Each thread: 3 outputs (3e x 1f).
//   M[e,d]  = (1/32) * sum_v H[v,e]*x[v,d]
//   ED[e,f] = relu(sum_d M[e,d]*W[f,d] + b[f])  -> h_e
//   partial c -> Cscratch (stcg); last quarter-block per graph via
//   atom.add.acq_rel.gpu counter sums partials in fixed order, writes c.
// Output buffer: [ c (B*D) | h_e (B*E*D) ]
//
// R9: occupancy was grid-limited (1024 blocks x 4 warps = 27.7 warps/SM).
// 256 thr/block doubles resident warps (~86% occ) at the same 1%-imbalance
// grid; per-thread tile shrinks to 3 outputs, registers ~40.

constexpr int V   = 8192;
constexpr int E   = 48;
constexpr int D   = 64;
constexpr int B   = 256;
constexpr int NPG = V / B;        // 32 nodes per graph
constexpr int EQN = 4;            // e-quarters
constexpr int EPB = E / EQN;      // 12 edges per block
constexpr int NT  = 256;
constexpr int WS  = 68;           // W shared row stride (floats)

__device__ float Cscratch[EQN * B * D];   // partial-c scratch (L2 via stcg)
__device__ int   Ctr[B];                  // arrival counters (zero-init; reset by last block)

__global__ __launch_bounds__(NT, 6) void hgnn_main_kernel(
    const float* __restrict__ x,     // (V, D)
    const float* __restrict__ Hm,    // (V, E)
    const float* __restrict__ W,     // (D, D) row-major [f][d]
    const float* __restrict__ bias,  // (D,)
    float* __restrict__ out)         // [c | h_e]
{
    __shared__ float Ht[EPB * NPG];   // transposed H slice (1.5 KB)
    __shared__ float Ws[D * WS];      // W rows, stride 68 (17 KB)
    __shared__ float Ms[EPB * D];     // (3 KB)
    __shared__ float Sv[EPB];
    __shared__ float Bs[D];
    __shared__ float Cp[4][D];
    __shared__ int   isLast;

    const int b  = blockIdx.x;
    const int eq = blockIdx.y;
    const int t  = threadIdx.x;
    const int f  = t & 63;            // feature index
    const int g4 = t >> 6;            // 0..3 thread-group

    // ---- stage H slice transposed: Ht[e*32+v] = H[v, eq*12+e] ----
    {
        const float* hb = Hm + (size_t)b * NPG * E + eq * EPB;
        if (t < NPG * 3) {                       // 96 float4 loads
            int v = t / 3, g = t - (t / 3) * 3;
            float4 h = *(const float4*)(hb + v * E + g * 4);
            int e = g * 4;
            Ht[(e + 0) * NPG + v] = h.x;
            Ht[(e + 1) * NPG + v] = h.y;
            Ht[(e + 2) * NPG + v] = h.z;
            Ht[(e + 3) * NPG + v] = h.w;
        }
        // ---- stage W rows into Ws[f*68 + d] (coalesced LDG.128) ----
        #pragma unroll
        for (int i = t; i < D * D / 4; i += NT) {
            float4 w = ((const float4*)W)[i];
            int fw = i >> 4, d4 = (i & 15) * 4;
            *(float4*)&Ws[fw * WS + d4] = w;
        }
        if (t < D) Bs[t] = bias[t];
    }
    __syncthreads();

    // ---- s[e] = sum_v Ht[e,v] ----
    if (t < EPB) {
        const float4* hr = (const float4*)&Ht[t * NPG];
        float a0 = 0.f, a1 = 0.f;
        #pragma unroll
        for (int k = 0; k < NPG / 8; k++) {
            float4 h0 = hr[2 * k], h1 = hr[2 * k + 1];
            a0 += h0.x + h0.y + h0.z + h0.w;
            a1 += h1.x + h1.y + h1.z + h1.w;
        }
        Sv[t] = a0 + a1;
    }

    // ---- phase 1: M[e,f], e = j*4+g4, j=0..2 ----
    {
        float macc[3];
        #pragma unroll
        for (int j = 0; j < 3; j++) macc[j] = 0.f;

        #pragma unroll
        for (int vc = 0; vc < 2; vc++) {
            float xr[16];
            const float* xg = x + (size_t)b * NPG * D + (vc * 16) * D + f;
            #pragma unroll
            for (int v = 0; v < 16; v++) xr[v] = xg[v * D];   // coalesced

            #pragma unroll
            for (int j = 0; j < 3; j++) {
                int e = j * 4 + g4;
                const float4* hr = (const float4*)&Ht[e * NPG + vc * 16]; // bcast
                #pragma unroll
                for (int k = 0; k < 4; k++) {
                    float4 h = hr[k];
                    macc[j] = fmaf(h.x, xr[4 * k + 0], macc[j]);
                    macc[j] = fmaf(h.y, xr[4 * k + 1], macc[j]);
                    macc[j] = fmaf(h.z, xr[4 * k + 2], macc[j]);
                    macc[j] = fmaf(h.w, xr[4 * k + 3], macc[j]);
                }
            }
        }
        #pragma unroll
        for (int j = 0; j < 3; j++)
            Ms[(j * 4 + g4) * D + f] = macc[j] * (1.0f / NPG);
    }
    __syncthreads();

    // ---- phase 2: 3 outputs/thread, e = j*4+g4, fixed f ----
    {
        float acc[3];
        #pragma unroll
        for (int j = 0; j < 3; j++) acc[j] = Bs[f];

        #pragma unroll
        for (int dc = 0; dc < 4; dc++) {
            float4 wv[4];
            const float4* wr = (const float4*)&Ws[f * WS + dc * 16];
            #pragma unroll
            for (int k = 0; k < 4; k++) wv[k] = wr[k];        // conflict-free

            #pragma unroll
            for (int j = 0; j < 3; j++) {
                int e = j * 4 + g4;
                const float4* mr = (const float4*)&Ms[e * D + dc * 16]; // bcast
                #pragma unroll
                for (int k = 0; k < 4; k++) {
                    float4 m = mr[k];
                    acc[j] = fmaf(m.x, wv[k].x, acc[j]);
                    acc[j] = fmaf(m.y, wv[k].y, acc[j]);
                    acc[j] = fmaf(m.z, wv[k].z, acc[j]);
                    acc[j] = fmaf(m.w, wv[k].w, acc[j]);
                }
            }
        }

        // relu, h_e store, c fold
        float cacc = 0.f;
        float* he = out + (size_t)B * D + ((size_t)b * E + eq * EPB) * D;
        #pragma unroll
        for (int j = 0; j < 3; j++) {
            int e = j * 4 + g4;
            float r = fmaxf(acc[j], 0.f);
            he[e * D + f] = r;                                // coalesced
            cacc = fmaf(Sv[e], r, cacc);
        }
        Cp[g4][f] = cacc;
    }
    __syncthreads();

    // ---- partial c -> L2 scratch; last quarter-block reduces ----
    if (t < D) {
        float c = Cp[0][t] + Cp[1][t] + Cp[2][t] + Cp[3][t];
        __stcg(&Cscratch[(eq * B + b) * D + t], c);
    }
    __syncthreads();   // all partial stores happen-before t0's release

    if (t == 0) {
        int old;
        asm volatile("atom.add.acq_rel.gpu.global.s32 %0, [%1], 1;"
                     : "=r"(old) : "l"(&Ctr[b]) : "memory");
        isLast = (old == EQN - 1);
    }
    __syncthreads();   // t0's acquire happens-before consumer loads

    if (isLast) {
        if (t < D) {
            float s = __ldcg(&Cscratch[b * D + t])
                    + __ldcg(&Cscratch[(B + b) * D + t])
                    + __ldcg(&Cscratch[(2 * B + b) * D + t])
                    + __ldcg(&Cscratch[(3 * B + b) * D + t]);
            out[b * D + t] = s * (1.0f / (NPG * E));
        }
        if (t == 0) Ctr[b] = 0;          // clean for next replay
    }
}

extern "C" void kernel_launch(void* const* d_in, const int* in_sizes, int n_in,
                              void* d_out, int out_size) {
    const float* x    = (const float*)d_in[0];   // (V,D)
    const float* Hm   = (const float*)d_in[1];   // (V,E)
    const float* W    = (const float*)d_in[2];   // (D,D)
    const float* bias = (const float*)d_in[3];   // (D,)
    float* out = (float*)d_out;

    dim3 grid(B, EQN);
    hgnn_main_kernel<<<grid, NT>>>(x, Hm, W, bias, out);
}

// round 10
// speedup vs baseline: 1.0688x; 1.0688x over previous
#include <cuda_runtime.h>
#include <cuda_bf16.h>

// HGNN forward, 2 kernels via associativity: (H^T x) W^T == H^T (x W^T).
//   Kernel A: Y = x @ W^T            (graph-independent, 8192x64 @ 64x64)
//   Kernel B: per (graph, e-quarter):
//     ED[e,f] = relu( (1/32) sum_v H[v,e] * Y[v,f] + b[f] )   -> h_e
//     partial c -> Cscratch; last quarter-block per graph (acq_rel atomic
//     counter) sums partials in fixed order, writes c.
// Output buffer: [ c (B*D) | h_e (B*E*D) ]

constexpr int V   = 8192;
constexpr int E   = 48;
constexpr int D   = 64;
constexpr int B   = 256;
constexpr int NPG = V / B;        // 32 nodes per graph
constexpr int EQN = 4;            // e-quarters
constexpr int EPB = E / EQN;      // 12 edges per block
constexpr int WS  = 68;           // W shared row stride (floats)

__device__ float Ybuf[V * D];             // 2 MB: Y = x @ W^T
__device__ float Cscratch[EQN * B * D];   // partial-c scratch (L2 via stcg)
__device__ int   Ctr[B];                  // arrival counters (zero-init; reset by last block)

// ---------------- Kernel A: Y = x @ W^T ----------------
// 1024 blocks x 128 threads; each block computes an 8-row Y tile.
// Thread: f = t&63, g = t>>6; outputs Y[v, f] for v = g*4 + j, j=0..3.
constexpr int NTA = 128;
constexpr int VTA = 8;            // v-rows per block

__global__ __launch_bounds__(NTA, 12) void hgnn_y_kernel(
    const float* __restrict__ x,     // (V, D)
    const float* __restrict__ W)     // (D, D) row-major [f][d]
{
    __shared__ float Xs[VTA * D];     // 2 KB
    __shared__ float Ws[D * WS];      // 17 KB, Ws[f*68+d] = W[f*64+d]

    const int t  = threadIdx.x;
    const int f  = t & 63;
    const int g  = t >> 6;            // 0..1
    const int vb = blockIdx.x * VTA;

    // stage x tile (coalesced) and W rows (coalesced)
    {
        const float4* xg = (const float4*)(x + (size_t)vb * D);
        if (t < VTA * D / 4) ((float4*)Xs)[t] = xg[t];
        #pragma unroll
        for (int i = t; i < D * D / 4; i += NTA) {
            float4 w = ((const float4*)W)[i];
            int fw = i >> 4, d4 = (i & 15) * 4;
            *(float4*)&Ws[fw * WS + d4] = w;
        }
    }
    __syncthreads();

    float acc[4] = {0.f, 0.f, 0.f, 0.f};
    #pragma unroll
    for (int dc = 0; dc < 4; dc++) {
        float4 wv[4];
        const float4* wr = (const float4*)&Ws[f * WS + dc * 16];
        #pragma unroll
        for (int k = 0; k < 4; k++) wv[k] = wr[k];

        #pragma unroll
        for (int j = 0; j < 4; j++) {
            int v = g * 4 + j;
            const float4* mr = (const float4*)&Xs[v * D + dc * 16];   // bcast
            #pragma unroll
            for (int k = 0; k < 4; k++) {
                float4 m = mr[k];
                acc[j] = fmaf(m.x, wv[k].x, acc[j]);
                acc[j] = fmaf(m.y, wv[k].y, acc[j]);
                acc[j] = fmaf(m.z, wv[k].z, acc[j]);
                acc[j] = fmaf(m.w, wv[k].w, acc[j]);
            }
        }
    }
    #pragma unroll
    for (int j = 0; j < 4; j++)
        __stcg(&Ybuf[(size_t)(vb + g * 4 + j) * D + f], acc[j]);      // coalesced
}

// ---------------- Kernel B: aggregate + relu + outputs ----------------
constexpr int NTB = 128;

__global__ __launch_bounds__(NTB, 8) void hgnn_agg_kernel(
    const float* __restrict__ Hm,    // (V, E)
    const float* __restrict__ bias,  // (D,)
    float* __restrict__ out)         // [c | h_e]
{
    __shared__ float Ht[EPB * NPG];   // transposed H slice (1.5 KB)
    __shared__ float Sv[EPB];
    __shared__ float Bs[D];
    __shared__ float Cp[2][D];
    __shared__ int   isLast;

    const int b  = blockIdx.x;
    const int eq = blockIdx.y;
    const int t  = threadIdx.x;
    const int f  = t & 63;
    const int g  = t >> 6;            // 0..1

    // ---- stage H slice transposed: Ht[e*32+v] = H[v, eq*12+e] ----
    {
        const float* hb = Hm + (size_t)b * NPG * E + eq * EPB;
        if (t < NPG * 3) {                       // 96 float4 loads
            int v = t / 3, gg = t - (t / 3) * 3;
            float4 h = *(const float4*)(hb + v * E + gg * 4);
            int e = gg * 4;
            Ht[(e + 0) * NPG + v] = h.x;
            Ht[(e + 1) * NPG + v] = h.y;
            Ht[(e + 2) * NPG + v] = h.z;
            Ht[(e + 3) * NPG + v] = h.w;
        }
        if (t < D) Bs[t] = bias[t];
    }
    __syncthreads();

    // ---- s[e] = sum_v Ht[e,v] ----
    if (t < EPB) {
        const float4* hr = (const float4*)&Ht[t * NPG];
        float a0 = 0.f, a1 = 0.f;
        #pragma unroll
        for (int k = 0; k < NPG / 8; k++) {
            float4 h0 = hr[2 * k], h1 = hr[2 * k + 1];
            a0 += h0.x + h0.y + h0.z + h0.w;
            a1 += h1.x + h1.y + h1.z + h1.w;
        }
        Sv[t] = a0 + a1;
    }
    __syncthreads();

    // ---- ED[e,f] = relu((1/32) sum_v Ht[e,v]*Y[v,f] + b[f]);  e = j*2+g ----
    float acc[6];
    #pragma unroll
    for (int j = 0; j < 6; j++) acc[j] = 0.f;

    #pragma unroll
    for (int vc = 0; vc < 2; vc++) {
        float yr[16];
        const float* yg = Ybuf + ((size_t)b * NPG + vc * 16) * D + f;
        #pragma unroll
        for (int v = 0; v < 16; v++) yr[v] = yg[v * D];   // coalesced

        #pragma unroll
        for (int j = 0; j < 6; j++) {
            int e = j * 2 + g;
            const float4* hr = (const float4*)&Ht[e * NPG + vc * 16]; // bcast
            #pragma unroll
            for (int k = 0; k < 4; k++) {
                float4 h = hr[k];
                acc[j] = fmaf(h.x, yr[4 * k + 0], acc[j]);
                acc[j] = fmaf(h.y, yr[4 * k + 1], acc[j]);
                acc[j] = fmaf(h.z, yr[4 * k + 2], acc[j]);
                acc[j] = fmaf(h.w, yr[4 * k + 3], acc[j]);
            }
        }
    }

    // ---- relu, h_e store, c fold ----
    {
        float cacc = 0.f;
        const float bf = Bs[f];
        float* he = out + (size_t)B * D + ((size_t)b * E + eq * EPB) * D;
        #pragma unroll
        for (int j = 0; j < 6; j++) {
            int e = j * 2 + g;
            float r = fmaxf(fmaf(acc[j], 1.0f / NPG, bf), 0.f);
            he[e * D + f] = r;                            // coalesced
            cacc = fmaf(Sv[e], r, cacc);
        }
        Cp[g][f] = cacc;
    }
    __syncthreads();

    // ---- partial c -> L2 scratch; last quarter-block per graph reduces ----
    if (t < D) {
        float c = Cp[0][t] + Cp[1][t];
        __stcg(&Cscratch[(eq * B + b) * D + t], c);
    }
    __syncthreads();   // all partial stores happen-before t0's release

    if (t == 0) {
        int old;
        asm volatile("atom.add.acq_rel.gpu.global.s32 %0, [%1], 1;"
                     : "=r"(old) : "l"(&Ctr[b]) : "memory");
        isLast = (old == EQN - 1);
    }
    __syncthreads();   // t0's acquire happens-before consumer loads

    if (isLast) {
        if (t < D) {
            float s = __ldcg(&Cscratch[b * D + t])
                    + __ldcg(&Cscratch[(B + b) * D + t])
                    + __ldcg(&Cscratch[(2 * B + b) * D + t])
                    + __ldcg(&Cscratch[(3 * B + b) * D + t]);
            out[b * D + t] = s * (1.0f / (NPG * E));
        }
        if (t == 0) Ctr[b] = 0;          // clean for next replay
    }
}

extern "C" void kernel_launch(void* const* d_in, const int* in_sizes, int n_in,
                              void* d_out, int out_size) {
    const float* x    = (const float*)d_in[0];   // (V,D)
    const float* Hm   = (const float*)d_in[1];   // (V,E)
    const float* W    = (const float*)d_in[2];   // (D,D)
    const float* bias = (const float*)d_in[3];   // (D,)
    float* out = (float*)d_out;

    hgnn_y_kernel<<<V / VTA, NTA>>>(x, W);
    dim3 grid(B, EQN);
    hgnn_agg_kernel<<<grid, NTB>>>(Hm, bias, out);
}